// round 1
// baseline (speedup 1.0000x reference)
#include <cuda_runtime.h>
#include <cuda_bf16.h>
#include <math.h>

// ---------------------------------------------------------------------------
// FrozenLSLModel: the whole scan collapses to a 64x64 (pred, out_pos) table.
//   K0: decoder table  pred[s] for s in 0..63
//   K1: H1[p*64+i,:] = relu(Wi0[64+p] + Wi0[i] + bi0); valid[p,i] via Wv*
//   K2: H2 = relu(H1 @ Wi1 + bi1)            [4096,768]x[768,768]  (dominant)
//   K3: logits = H2 @ Wi2 + bi2 -> argmax -> idx[4096]
//   K4: out[b,i] = a_bits[b, idx[p_b,i]] * valid[p_b,i],  p_b = pred[shift[b]]
// ---------------------------------------------------------------------------

#define HID 768
#define BITS 64
#define T_ROWS (BITS * BITS)   // 4096 table rows

__device__ float g_H1[T_ROWS * HID];
__device__ float g_H2[T_ROWS * HID];
__device__ float g_valid[T_ROWS];
__device__ int   g_idx[T_ROWS];
__device__ int   g_pred[BITS];

// ---------------------------------------------------------------------------
// K0: shift decoder for all 64 possible shift_amount values.
// One block per s, 256 threads.
// ---------------------------------------------------------------------------
__global__ __launch_bounds__(256)
void decoder_kernel(const float* __restrict__ Ws0, const float* __restrict__ bs0,
                    const float* __restrict__ Ws1, const float* __restrict__ bs1,
                    const float* __restrict__ Ws2, const float* __restrict__ bs2) {
    int s = blockIdx.x;
    int tid = threadIdx.x;
    __shared__ float h0[HID];
    __shared__ float h1[HID];
    __shared__ float lg[BITS];

    // layer 0: shift_bits(s) has only bits 0..5 set (s < 64)
    for (int j = tid; j < HID; j += 256) {
        float v = bs0[j];
        #pragma unroll
        for (int k = 0; k < 6; k++)
            if ((s >> k) & 1) v += Ws0[k * HID + j];
        h0[j] = fmaxf(v, 0.f);
    }
    __syncthreads();

    // layer 1: 768 outputs, 3 per thread
    {
        float a0 = bs1[tid], a1 = bs1[tid + 256], a2 = bs1[tid + 512];
        for (int k = 0; k < HID; k++) {
            float h = h0[k];
            const float* row = Ws1 + (size_t)k * HID;
            a0 = fmaf(h, row[tid], a0);
            a1 = fmaf(h, row[tid + 256], a1);
            a2 = fmaf(h, row[tid + 512], a2);
        }
        h1[tid]       = fmaxf(a0, 0.f);
        h1[tid + 256] = fmaxf(a1, 0.f);
        h1[tid + 512] = fmaxf(a2, 0.f);
    }
    __syncthreads();

    // layer 2: 64 logits
    if (tid < BITS) {
        float a = bs2[tid];
        for (int k = 0; k < HID; k++)
            a = fmaf(h1[k], Ws2[(size_t)k * BITS + tid], a);
        lg[tid] = a;
    }
    __syncthreads();

    if (tid == 0) {
        float best = lg[0]; int bi = 0;
        for (int c = 1; c < BITS; c++)
            if (lg[c] > best) { best = lg[c]; bi = c; }
        g_pred[s] = bi;
    }
}

// ---------------------------------------------------------------------------
// K1: build H1 rows + validity table. One block per (p,i), 256 threads.
// ---------------------------------------------------------------------------
__global__ __launch_bounds__(256)
void table_kernel(const float* __restrict__ Wi0, const float* __restrict__ bi0,
                  const float* __restrict__ Wv0, const float* __restrict__ bv0,
                  const float* __restrict__ Wv1, const float* __restrict__ bv1) {
    int t = blockIdx.x;
    int p = t >> 6;
    int i = t & 63;
    int tid = threadIdx.x;

    const float* rp = Wi0 + (size_t)(BITS + p) * HID;
    const float* ri = Wi0 + (size_t)i * HID;
    float* dst = g_H1 + (size_t)t * HID;
    for (int j = tid; j < HID; j += 256)
        dst[j] = fmaxf(rp[j] + ri[j] + bi0[j], 0.f);

    const float* vp = Wv0 + (size_t)(BITS + p) * (HID / 2);
    const float* vi = Wv0 + (size_t)i * (HID / 2);
    float part = 0.f;
    for (int j = tid; j < HID / 2; j += 256)
        part += fmaxf(vp[j] + vi[j] + bv0[j], 0.f) * Wv1[j];

    __shared__ float red[256];
    red[tid] = part;
    __syncthreads();
    for (int off = 128; off > 0; off >>= 1) {
        if (tid < off) red[tid] += red[tid + off];
        __syncthreads();
    }
    if (tid == 0) {
        float v = red[0] + bv1[0];
        g_valid[t] = 1.f / (1.f + expf(-v));
    }
}

// ---------------------------------------------------------------------------
// K2: H2 = relu(H1 @ Wi1 + bi1).  M=4096, N=768, K=768.
// 128x128 tile, BK=8, 256 threads, 8x8 per thread.
// ---------------------------------------------------------------------------
__global__ __launch_bounds__(256)
void gemm1_kernel(const float* __restrict__ Wi1, const float* __restrict__ bi1) {
    const int BM = 128, BN = 128, BK = 8;
    __shared__ float As[BK][BM];
    __shared__ float Bs[BK][BN];

    int tid = threadIdx.x;
    int m0 = blockIdx.y * BM;
    int n0 = blockIdx.x * BN;
    int trow = tid >> 4;        // 0..15
    int tcol = tid & 15;        // 0..15

    float acc[8][8] = {};

    int aRow = tid >> 1;        // 0..127
    int aK   = (tid & 1) * 4;   // 0 or 4
    int bRow = tid >> 5;        // 0..7
    int bCol = (tid & 31) * 4;  // 0..124

    const float* Ag = g_H1 + (size_t)(m0 + aRow) * HID + aK;
    const float* Bg = Wi1 + (size_t)bRow * HID + n0 + bCol;

    for (int kt = 0; kt < HID; kt += BK) {
        float4 av = *(const float4*)(Ag + kt);
        float4 bv = *(const float4*)(Bg + (size_t)kt * HID);
        As[aK + 0][aRow] = av.x;
        As[aK + 1][aRow] = av.y;
        As[aK + 2][aRow] = av.z;
        As[aK + 3][aRow] = av.w;
        *(float4*)&Bs[bRow][bCol] = bv;
        __syncthreads();

        #pragma unroll
        for (int k = 0; k < BK; k++) {
            float aF[8], bF[8];
            #pragma unroll
            for (int m = 0; m < 8; m++) aF[m] = As[k][trow * 8 + m];
            #pragma unroll
            for (int n = 0; n < 8; n++) bF[n] = Bs[k][tcol * 8 + n];
            #pragma unroll
            for (int m = 0; m < 8; m++)
                #pragma unroll
                for (int n = 0; n < 8; n++)
                    acc[m][n] = fmaf(aF[m], bF[n], acc[m][n]);
        }
        __syncthreads();
    }

    #pragma unroll
    for (int m = 0; m < 8; m++) {
        int row = m0 + trow * 8 + m;
        int col = n0 + tcol * 8;
        float* Cg = g_H2 + (size_t)row * HID + col;
        float4 o0, o1;
        o0.x = fmaxf(acc[m][0] + bi1[col + 0], 0.f);
        o0.y = fmaxf(acc[m][1] + bi1[col + 1], 0.f);
        o0.z = fmaxf(acc[m][2] + bi1[col + 2], 0.f);
        o0.w = fmaxf(acc[m][3] + bi1[col + 3], 0.f);
        o1.x = fmaxf(acc[m][4] + bi1[col + 4], 0.f);
        o1.y = fmaxf(acc[m][5] + bi1[col + 5], 0.f);
        o1.z = fmaxf(acc[m][6] + bi1[col + 6], 0.f);
        o1.w = fmaxf(acc[m][7] + bi1[col + 7], 0.f);
        *(float4*)(Cg)     = o0;
        *(float4*)(Cg + 4) = o1;
    }
}

// ---------------------------------------------------------------------------
// K3: logits = H2 @ Wi2 + bi2 ; per-row argmax -> g_idx.
// M=4096 in blocks of 32 rows, full N=64 per block, BK=32, 256 threads.
// ---------------------------------------------------------------------------
__global__ __launch_bounds__(256)
void gemm2_kernel(const float* __restrict__ Wi2, const float* __restrict__ bi2) {
    const int BM = 32, BN = 64, BK = 32;
    __shared__ float As[BK][BM];
    __shared__ float Bs[BK][BN];
    __shared__ float Ls[BM][BN + 1];

    int tid = threadIdx.x;
    int m0 = blockIdx.x * BM;
    int trow = tid >> 4;        // 0..15 -> 2 rows each
    int tcol = tid & 15;        // 0..15 -> 4 cols each

    float acc[2][4] = {};

    int aRow = tid >> 3;        // 0..31
    int aK   = (tid & 7) * 4;   // 0..28
    int bRow = tid >> 4;        // 0..15 (two passes)
    int bCol = (tid & 15) * 4;  // 0..60

    const float* Ag = g_H2 + (size_t)(m0 + aRow) * HID + aK;

    for (int kt = 0; kt < HID; kt += BK) {
        float4 av = *(const float4*)(Ag + kt);
        As[aK + 0][aRow] = av.x;
        As[aK + 1][aRow] = av.y;
        As[aK + 2][aRow] = av.z;
        As[aK + 3][aRow] = av.w;
        #pragma unroll
        for (int r = 0; r < 2; r++) {
            int br = bRow + r * 16;
            float4 bv = *(const float4*)(Wi2 + (size_t)(kt + br) * BITS + bCol);
            *(float4*)&Bs[br][bCol] = bv;
        }
        __syncthreads();

        #pragma unroll
        for (int k = 0; k < BK; k++) {
            float aF[2], bF[4];
            aF[0] = As[k][trow * 2 + 0];
            aF[1] = As[k][trow * 2 + 1];
            #pragma unroll
            for (int n = 0; n < 4; n++) bF[n] = Bs[k][tcol * 4 + n];
            #pragma unroll
            for (int m = 0; m < 2; m++)
                #pragma unroll
                for (int n = 0; n < 4; n++)
                    acc[m][n] = fmaf(aF[m], bF[n], acc[m][n]);
        }
        __syncthreads();
    }

    #pragma unroll
    for (int m = 0; m < 2; m++)
        #pragma unroll
        for (int n = 0; n < 4; n++)
            Ls[trow * 2 + m][tcol * 4 + n] = acc[m][n] + bi2[tcol * 4 + n];
    __syncthreads();

    if (tid < BM) {
        float best = Ls[tid][0]; int bi = 0;
        for (int c = 1; c < BITS; c++) {
            float v = Ls[tid][c];
            if (v > best) { best = v; bi = c; }
        }
        g_idx[m0 + tid] = bi;
    }
}

// ---------------------------------------------------------------------------
// K4: final gather + scale.  out[b,i] = a_bits[b, idx[p,i]] * valid[p,i].
// ---------------------------------------------------------------------------
__global__ __launch_bounds__(256)
void out_kernel(const float* __restrict__ a_bits, const int* __restrict__ shift,
                float* __restrict__ out, int total) {
    int idx = blockIdx.x * 256 + threadIdx.x;
    if (idx >= total) return;
    int b = idx >> 6;
    int i = idx & 63;
    int p = g_pred[shift[b]];
    int t = (p << 6) | i;
    out[idx] = a_bits[((size_t)b << 6) + g_idx[t]] * g_valid[t];
}

// ---------------------------------------------------------------------------
extern "C" void kernel_launch(void* const* d_in, const int* in_sizes, int n_in,
                              void* d_out, int out_size) {
    const float* a_bits = (const float*)d_in[0];
    const int*   shift  = (const int*)d_in[1];
    const float* Ws0 = (const float*)d_in[2];
    const float* bs0 = (const float*)d_in[3];
    const float* Ws1 = (const float*)d_in[4];
    const float* bs1 = (const float*)d_in[5];
    const float* Ws2 = (const float*)d_in[6];
    const float* bs2 = (const float*)d_in[7];
    const float* Wi0 = (const float*)d_in[8];
    const float* bi0 = (const float*)d_in[9];
    const float* Wi1 = (const float*)d_in[10];
    const float* bi1 = (const float*)d_in[11];
    const float* Wi2 = (const float*)d_in[12];
    const float* bi2 = (const float*)d_in[13];
    const float* Wv0 = (const float*)d_in[14];
    const float* bv0 = (const float*)d_in[15];
    const float* Wv1 = (const float*)d_in[16];
    const float* bv1 = (const float*)d_in[17];
    float* out = (float*)d_out;

    int B = in_sizes[1];           // 32768
    int total = B * BITS;

    decoder_kernel<<<BITS, 256>>>(Ws0, bs0, Ws1, bs1, Ws2, bs2);
    table_kernel<<<T_ROWS, 256>>>(Wi0, bi0, Wv0, bv0, Wv1, bv1);

    dim3 g1(HID / 128, T_ROWS / 128);   // (6, 32)
    gemm1_kernel<<<g1, 256>>>(Wi1, bi1);

    gemm2_kernel<<<T_ROWS / 32, 256>>>(Wi2, bi2);

    out_kernel<<<(total + 255) / 256, 256>>>(a_bits, shift, out, total);
}

// round 2
// speedup vs baseline: 1.5845x; 1.5845x over previous
#include <cuda_runtime.h>
#include <cuda_bf16.h>
#include <math.h>

// ---------------------------------------------------------------------------
// FrozenLSLModel collapses to a (pred, out_pos) table. R2: compact the pred
// axis to the u <= 64 values the decoder actually emits; split-K gemm2;
// double-buffered gemm1.
// ---------------------------------------------------------------------------

#define HID 768
#define BITS 64
#define T_ROWS (BITS * BITS)
#define KSLICES 4
#define KSLICE (HID / KSLICES)   // 192

__device__ float g_H1[T_ROWS * HID];
__device__ float g_H2[T_ROWS * HID];
__device__ float g_valid[T_ROWS];
__device__ int   g_idx[T_ROWS];
__device__ int   g_pred[BITS];
__device__ int   g_u;                    // number of distinct preds
__device__ int   g_plist[BITS];          // slot -> p
__device__ int   g_pred_slot[BITS];      // s -> slot
__device__ float g_part[KSLICES][T_ROWS][BITS];

// ---------------------------------------------------------------------------
// K0: shift decoder for all 64 possible shift values.
// ---------------------------------------------------------------------------
__global__ __launch_bounds__(256)
void decoder_kernel(const float* __restrict__ Ws0, const float* __restrict__ bs0,
                    const float* __restrict__ Ws1, const float* __restrict__ bs1,
                    const float* __restrict__ Ws2, const float* __restrict__ bs2) {
    int s = blockIdx.x;
    int tid = threadIdx.x;
    __shared__ float h0[HID];
    __shared__ float h1[HID];
    __shared__ float lg[BITS];

    for (int j = tid; j < HID; j += 256) {
        float v = bs0[j];
        #pragma unroll
        for (int k = 0; k < 6; k++)
            if ((s >> k) & 1) v += Ws0[k * HID + j];
        h0[j] = fmaxf(v, 0.f);
    }
    __syncthreads();

    {
        float a0 = bs1[tid], a1 = bs1[tid + 256], a2 = bs1[tid + 512];
        for (int k = 0; k < HID; k++) {
            float h = h0[k];
            const float* row = Ws1 + (size_t)k * HID;
            a0 = fmaf(h, row[tid], a0);
            a1 = fmaf(h, row[tid + 256], a1);
            a2 = fmaf(h, row[tid + 512], a2);
        }
        h1[tid]       = fmaxf(a0, 0.f);
        h1[tid + 256] = fmaxf(a1, 0.f);
        h1[tid + 512] = fmaxf(a2, 0.f);
    }
    __syncthreads();

    if (tid < BITS) {
        float a = bs2[tid];
        for (int k = 0; k < HID; k++)
            a = fmaf(h1[k], Ws2[(size_t)k * BITS + tid], a);
        lg[tid] = a;
    }
    __syncthreads();

    if (tid == 0) {
        float best = lg[0]; int bi = 0;
        for (int c = 1; c < BITS; c++)
            if (lg[c] > best) { best = lg[c]; bi = c; }
        g_pred[s] = bi;
    }
}

// ---------------------------------------------------------------------------
// K0b: compact distinct preds -> slots (single thread; trivial work).
// ---------------------------------------------------------------------------
__global__ void compact_kernel() {
    int used[BITS];
    int slot[BITS];
    for (int p = 0; p < BITS; p++) used[p] = 0;
    for (int s = 0; s < BITS; s++) used[g_pred[s]] = 1;
    int u = 0;
    for (int p = 0; p < BITS; p++) {
        if (used[p]) { g_plist[u] = p; slot[p] = u; u++; }
    }
    g_u = u;
    for (int s = 0; s < BITS; s++) g_pred_slot[s] = slot[g_pred[s]];
}

// ---------------------------------------------------------------------------
// K1: build compacted H1 rows + validity. Block t -> (slot = t>>6, i = t&63).
// ---------------------------------------------------------------------------
__global__ __launch_bounds__(256)
void table_kernel(const float* __restrict__ Wi0, const float* __restrict__ bi0,
                  const float* __restrict__ Wv0, const float* __restrict__ bv0,
                  const float* __restrict__ Wv1, const float* __restrict__ bv1) {
    int t = blockIdx.x;
    int sl = t >> 6;
    if (sl >= g_u) return;
    int p = g_plist[sl];
    int i = t & 63;
    int tid = threadIdx.x;

    const float* rp = Wi0 + (size_t)(BITS + p) * HID;
    const float* ri = Wi0 + (size_t)i * HID;
    float* dst = g_H1 + (size_t)t * HID;
    for (int j = tid; j < HID; j += 256)
        dst[j] = fmaxf(rp[j] + ri[j] + bi0[j], 0.f);

    const float* vp = Wv0 + (size_t)(BITS + p) * (HID / 2);
    const float* vi = Wv0 + (size_t)i * (HID / 2);
    float part = 0.f;
    for (int j = tid; j < HID / 2; j += 256)
        part += fmaxf(vp[j] + vi[j] + bv0[j], 0.f) * Wv1[j];

    __shared__ float red[256];
    red[tid] = part;
    __syncthreads();
    for (int off = 128; off > 0; off >>= 1) {
        if (tid < off) red[tid] += red[tid + off];
        __syncthreads();
    }
    if (tid == 0) {
        float v = red[0] + bv1[0];
        g_valid[t] = 1.f / (1.f + expf(-v));
    }
}

// ---------------------------------------------------------------------------
// K2: H2 = relu(H1 @ Wi1 + bi1). 128x128 tile, BK=8, double-buffered smem.
// ---------------------------------------------------------------------------
__global__ __launch_bounds__(256)
void gemm1_kernel(const float* __restrict__ Wi1, const float* __restrict__ bi1) {
    const int BM = 128, BN = 128, BK = 8;
    __shared__ float As[2][BK][BM];
    __shared__ float Bs[2][BK][BN];

    int m0 = blockIdx.y * BM;
    if (m0 >= g_u * BITS) return;
    int tid = threadIdx.x;
    int n0 = blockIdx.x * BN;
    int trow = tid >> 4;
    int tcol = tid & 15;

    float acc[8][8] = {};

    int aRow = tid >> 1;
    int aK   = (tid & 1) * 4;
    int bRow = tid >> 5;
    int bCol = (tid & 31) * 4;

    const float* Ag = g_H1 + (size_t)(m0 + aRow) * HID + aK;
    const float* Bg = Wi1 + (size_t)bRow * HID + n0 + bCol;

    // prime buffer 0
    {
        float4 av = *(const float4*)(Ag);
        float4 bv = *(const float4*)(Bg);
        As[0][aK + 0][aRow] = av.x;
        As[0][aK + 1][aRow] = av.y;
        As[0][aK + 2][aRow] = av.z;
        As[0][aK + 3][aRow] = av.w;
        *(float4*)&Bs[0][bRow][bCol] = bv;
    }
    __syncthreads();

    int cur = 0;
    for (int kt = 0; kt < HID; kt += BK) {
        float4 av, bv;
        bool more = (kt + BK) < HID;
        if (more) {
            av = *(const float4*)(Ag + kt + BK);
            bv = *(const float4*)(Bg + (size_t)(kt + BK) * HID);
        }

        #pragma unroll
        for (int k = 0; k < BK; k++) {
            float aF[8], bF[8];
            #pragma unroll
            for (int m = 0; m < 8; m++) aF[m] = As[cur][k][trow * 8 + m];
            #pragma unroll
            for (int n = 0; n < 8; n++) bF[n] = Bs[cur][k][tcol * 8 + n];
            #pragma unroll
            for (int m = 0; m < 8; m++)
                #pragma unroll
                for (int n = 0; n < 8; n++)
                    acc[m][n] = fmaf(aF[m], bF[n], acc[m][n]);
        }

        if (more) {
            int nxt = cur ^ 1;
            As[nxt][aK + 0][aRow] = av.x;
            As[nxt][aK + 1][aRow] = av.y;
            As[nxt][aK + 2][aRow] = av.z;
            As[nxt][aK + 3][aRow] = av.w;
            *(float4*)&Bs[nxt][bRow][bCol] = bv;
        }
        __syncthreads();
        cur ^= 1;
    }

    #pragma unroll
    for (int m = 0; m < 8; m++) {
        int row = m0 + trow * 8 + m;
        int col = n0 + tcol * 8;
        float* Cg = g_H2 + (size_t)row * HID + col;
        float4 o0, o1;
        o0.x = fmaxf(acc[m][0] + bi1[col + 0], 0.f);
        o0.y = fmaxf(acc[m][1] + bi1[col + 1], 0.f);
        o0.z = fmaxf(acc[m][2] + bi1[col + 2], 0.f);
        o0.w = fmaxf(acc[m][3] + bi1[col + 3], 0.f);
        o1.x = fmaxf(acc[m][4] + bi1[col + 4], 0.f);
        o1.y = fmaxf(acc[m][5] + bi1[col + 5], 0.f);
        o1.z = fmaxf(acc[m][6] + bi1[col + 6], 0.f);
        o1.w = fmaxf(acc[m][7] + bi1[col + 7], 0.f);
        *(float4*)(Cg)     = o0;
        *(float4*)(Cg + 4) = o1;
    }
}

// ---------------------------------------------------------------------------
// K3a: split-K logits partials. Tile 64 rows x 64 cols, 4x4 per thread.
// grid = (M/64, KSLICES).
// ---------------------------------------------------------------------------
__global__ __launch_bounds__(256)
void gemm2_kernel(const float* __restrict__ Wi2) {
    const int BM = 64, BK = 16;
    int m0 = blockIdx.x * BM;
    if (m0 >= g_u * BITS) return;
    int slice = blockIdx.y;
    int k0 = slice * KSLICE;

    __shared__ float As[BK][BM];
    __shared__ float Bs[BK][BITS];

    int tid = threadIdx.x;
    int ty = tid >> 4;          // 0..15 -> rows ty*4..ty*4+3
    int tx = tid & 15;          // 0..15 -> cols tx*4..tx*4+3

    int aRow = tid >> 2;        // 0..63
    int aK   = (tid & 3) * 4;   // 0..12
    int bRow = tid >> 4;        // 0..15
    int bCol = (tid & 15) * 4;  // 0..60

    float acc[4][4] = {};
    const float* Ag = g_H2 + (size_t)(m0 + aRow) * HID + k0 + aK;

    for (int kt = 0; kt < KSLICE; kt += BK) {
        float4 av = *(const float4*)(Ag + kt);
        As[aK + 0][aRow] = av.x;
        As[aK + 1][aRow] = av.y;
        As[aK + 2][aRow] = av.z;
        As[aK + 3][aRow] = av.w;
        float4 bv = *(const float4*)(Wi2 + (size_t)(k0 + kt + bRow) * BITS + bCol);
        *(float4*)&Bs[bRow][bCol] = bv;
        __syncthreads();

        #pragma unroll
        for (int k = 0; k < BK; k++) {
            float aF[4], bF[4];
            #pragma unroll
            for (int m = 0; m < 4; m++) aF[m] = As[k][ty * 4 + m];
            #pragma unroll
            for (int n = 0; n < 4; n++) bF[n] = Bs[k][tx * 4 + n];
            #pragma unroll
            for (int m = 0; m < 4; m++)
                #pragma unroll
                for (int n = 0; n < 4; n++)
                    acc[m][n] = fmaf(aF[m], bF[n], acc[m][n]);
        }
        __syncthreads();
    }

    #pragma unroll
    for (int m = 0; m < 4; m++) {
        float4 o;
        o.x = acc[m][0]; o.y = acc[m][1]; o.z = acc[m][2]; o.w = acc[m][3];
        *(float4*)&g_part[slice][m0 + ty * 4 + m][tx * 4] = o;
    }
}

// ---------------------------------------------------------------------------
// K3b: sum slices + bias, per-row argmax (first-max semantics, like jnp).
// One warp per row.
// ---------------------------------------------------------------------------
__global__ __launch_bounds__(256)
void argmax_kernel(const float* __restrict__ bi2) {
    int warp = threadIdx.x >> 5;
    int lane = threadIdx.x & 31;
    int row = blockIdx.x * 8 + warp;
    if (row >= g_u * BITS) return;

    float v0 = bi2[lane];
    float v1 = bi2[lane + 32];
    #pragma unroll
    for (int s = 0; s < KSLICES; s++) {
        v0 += g_part[s][row][lane];
        v1 += g_part[s][row][lane + 32];
    }
    float best = v0; int bi = lane;
    if (v1 > best) { best = v1; bi = lane + 32; }

    #pragma unroll
    for (int off = 16; off > 0; off >>= 1) {
        float ob = __shfl_down_sync(0xffffffff, best, off);
        int   oi = __shfl_down_sync(0xffffffff, bi, off);
        if (ob > best || (ob == best && oi < bi)) { best = ob; bi = oi; }
    }
    if (lane == 0) g_idx[row] = bi;
}

// ---------------------------------------------------------------------------
// K4: out[b,i] = a_bits[b, idx[slot,i]] * valid[slot,i]. float4-vectorized.
// ---------------------------------------------------------------------------
__global__ __launch_bounds__(256)
void out_kernel(const float* __restrict__ a_bits, const int* __restrict__ shift,
                float* __restrict__ out, int nquads) {
    int gid = blockIdx.x * 256 + threadIdx.x;
    if (gid >= nquads) return;
    int b = gid >> 4;
    int i0 = (gid & 15) * 4;
    int sl = g_pred_slot[shift[b]];
    int tb = (sl << 6) + i0;
    const float* arow = a_bits + ((size_t)b << 6);
    float4 o;
    o.x = arow[g_idx[tb + 0]] * g_valid[tb + 0];
    o.y = arow[g_idx[tb + 1]] * g_valid[tb + 1];
    o.z = arow[g_idx[tb + 2]] * g_valid[tb + 2];
    o.w = arow[g_idx[tb + 3]] * g_valid[tb + 3];
    ((float4*)out)[gid] = o;
}

// ---------------------------------------------------------------------------
extern "C" void kernel_launch(void* const* d_in, const int* in_sizes, int n_in,
                              void* d_out, int out_size) {
    const float* a_bits = (const float*)d_in[0];
    const int*   shift  = (const int*)d_in[1];
    const float* Ws0 = (const float*)d_in[2];
    const float* bs0 = (const float*)d_in[3];
    const float* Ws1 = (const float*)d_in[4];
    const float* bs1 = (const float*)d_in[5];
    const float* Ws2 = (const float*)d_in[6];
    const float* bs2 = (const float*)d_in[7];
    const float* Wi0 = (const float*)d_in[8];
    const float* bi0 = (const float*)d_in[9];
    const float* Wi1 = (const float*)d_in[10];
    const float* bi1 = (const float*)d_in[11];
    const float* Wi2 = (const float*)d_in[12];
    const float* bi2 = (const float*)d_in[13];
    const float* Wv0 = (const float*)d_in[14];
    const float* bv0 = (const float*)d_in[15];
    const float* Wv1 = (const float*)d_in[16];
    const float* bv1 = (const float*)d_in[17];
    float* out = (float*)d_out;

    int B = in_sizes[1];               // 32768
    int nquads = B * (BITS / 4);       // B*16 float4 stores

    decoder_kernel<<<BITS, 256>>>(Ws0, bs0, Ws1, bs1, Ws2, bs2);
    compact_kernel<<<1, 1>>>();
    table_kernel<<<T_ROWS, 256>>>(Wi0, bi0, Wv0, bv0, Wv1, bv1);

    dim3 g1(HID / 128, T_ROWS / 128);          // (6, 32), early-exit past u*64
    gemm1_kernel<<<g1, 256>>>(Wi1, bi1);

    dim3 g2(T_ROWS / 64, KSLICES);             // (64, 4)
    gemm2_kernel<<<g2, 256>>>(Wi2);
    argmax_kernel<<<T_ROWS / 8, 256>>>(bi2);

    out_kernel<<<(nquads + 255) / 256, 256>>>(a_bits, shift, out, nquads);
}

// round 3
// speedup vs baseline: 2.3375x; 1.4752x over previous
#include <cuda_runtime.h>
#include <cuda_bf16.h>
#include <math.h>

// ---------------------------------------------------------------------------
// FrozenLSLModel == (pred, out_pos) lookup table. u = #distinct decoder preds
// (measured ~10), so all GEMMs are tiny-M: partition for occupancy, not reuse.
//   decoder -> compact -> table(H1, valid)
//   gemm1 split-K=4 -> combine(relu+bias) -> gemm2 split-K=8 -> argmax -> out
// ---------------------------------------------------------------------------

#define HID 768
#define BITS 64
#define T_ROWS (BITS * BITS)

#define KS1 4                  // gemm1 K-slices
#define KSLICE1 (HID / KS1)    // 192
#define KS2 8                  // gemm2 K-slices
#define KSLICE2 (HID / KS2)    // 96

__device__ float g_H1[T_ROWS * HID];
__device__ float g_H2[T_ROWS * HID];
__device__ float g_p1[KS1][T_ROWS][HID];       // gemm1 partials
__device__ float g_part[KS2][T_ROWS][BITS];    // gemm2 partials
__device__ float g_valid[T_ROWS];
__device__ int   g_idx[T_ROWS];
__device__ int   g_pred[BITS];
__device__ int   g_u;
__device__ int   g_plist[BITS];
__device__ int   g_pred_slot[BITS];

// ---------------------------------------------------------------------------
// K0: shift decoder for all 64 possible shift values.
// ---------------------------------------------------------------------------
__global__ __launch_bounds__(256)
void decoder_kernel(const float* __restrict__ Ws0, const float* __restrict__ bs0,
                    const float* __restrict__ Ws1, const float* __restrict__ bs1,
                    const float* __restrict__ Ws2, const float* __restrict__ bs2) {
    int s = blockIdx.x;
    int tid = threadIdx.x;
    __shared__ float h0[HID];
    __shared__ float h1[HID];
    __shared__ float lg[BITS];

    for (int j = tid; j < HID; j += 256) {
        float v = bs0[j];
        #pragma unroll
        for (int k = 0; k < 6; k++)
            if ((s >> k) & 1) v += Ws0[k * HID + j];
        h0[j] = fmaxf(v, 0.f);
    }
    __syncthreads();

    {
        float a0 = bs1[tid], a1 = bs1[tid + 256], a2 = bs1[tid + 512];
        for (int k = 0; k < HID; k++) {
            float h = h0[k];
            const float* row = Ws1 + (size_t)k * HID;
            a0 = fmaf(h, row[tid], a0);
            a1 = fmaf(h, row[tid + 256], a1);
            a2 = fmaf(h, row[tid + 512], a2);
        }
        h1[tid]       = fmaxf(a0, 0.f);
        h1[tid + 256] = fmaxf(a1, 0.f);
        h1[tid + 512] = fmaxf(a2, 0.f);
    }
    __syncthreads();

    if (tid < BITS) {
        float a = bs2[tid];
        for (int k = 0; k < HID; k++)
            a = fmaf(h1[k], Ws2[(size_t)k * BITS + tid], a);
        lg[tid] = a;
    }
    __syncthreads();

    if (tid == 0) {
        float best = lg[0]; int bi = 0;
        for (int c = 1; c < BITS; c++)
            if (lg[c] > best) { best = lg[c]; bi = c; }
        g_pred[s] = bi;
    }
}

// ---------------------------------------------------------------------------
// K0b: compact distinct preds -> slots. 64 threads.
// ---------------------------------------------------------------------------
__global__ void compact_kernel() {
    __shared__ int used[BITS];
    __shared__ int slot[BITS];
    int tid = threadIdx.x;
    used[tid] = 0;
    __syncthreads();
    int pr = g_pred[tid];
    used[pr] = 1;                // benign race: all writers store 1
    __syncthreads();
    if (tid == 0) {
        int u = 0;
        for (int p = 0; p < BITS; p++)
            if (used[p]) { g_plist[u] = p; slot[p] = u; u++; }
        g_u = u;
    }
    __syncthreads();
    g_pred_slot[tid] = slot[pr];
}

// ---------------------------------------------------------------------------
// K1: build compacted H1 rows + validity. Block t -> (slot = t>>6, i = t&63).
// ---------------------------------------------------------------------------
__global__ __launch_bounds__(256)
void table_kernel(const float* __restrict__ Wi0, const float* __restrict__ bi0,
                  const float* __restrict__ Wv0, const float* __restrict__ bv0,
                  const float* __restrict__ Wv1, const float* __restrict__ bv1) {
    int t = blockIdx.x;
    int sl = t >> 6;
    if (sl >= g_u) return;
    int p = g_plist[sl];
    int i = t & 63;
    int tid = threadIdx.x;

    const float* rp = Wi0 + (size_t)(BITS + p) * HID;
    const float* ri = Wi0 + (size_t)i * HID;
    float* dst = g_H1 + (size_t)t * HID;
    for (int j = tid; j < HID; j += 256)
        dst[j] = fmaxf(rp[j] + ri[j] + bi0[j], 0.f);

    const float* vp = Wv0 + (size_t)(BITS + p) * (HID / 2);
    const float* vi = Wv0 + (size_t)i * (HID / 2);
    float part = 0.f;
    for (int j = tid; j < HID / 2; j += 256)
        part += fmaxf(vp[j] + vi[j] + bv0[j], 0.f) * Wv1[j];

    __shared__ float red[256];
    red[tid] = part;
    __syncthreads();
    for (int off = 128; off > 0; off >>= 1) {
        if (tid < off) red[tid] += red[tid + off];
        __syncthreads();
    }
    if (tid == 0) {
        float v = red[0] + bv1[0];
        g_valid[t] = 1.f / (1.f + expf(-v));
    }
}

// ---------------------------------------------------------------------------
// K2a: gemm1 split-K partials. BM=64, BN=64, BK=16, 4 K-slices.
// grid = (12, 64, 4). Thread tile 4x4.
// ---------------------------------------------------------------------------
__global__ __launch_bounds__(256)
void gemm1_kernel(const float* __restrict__ Wi1) {
    const int BK = 16;
    int m0 = blockIdx.y * 64;
    if (m0 >= g_u * BITS) return;
    int n0 = blockIdx.x * 64;
    int k0 = blockIdx.z * KSLICE1;

    __shared__ float As[BK][64];
    __shared__ float Bs[BK][64];

    int tid = threadIdx.x;
    int ty = tid >> 4;           // 0..15 -> rows ty*4..
    int tx = tid & 15;           // 0..15 -> cols tx*4..

    int aRow = tid >> 2;         // 0..63
    int aK   = (tid & 3) * 4;    // 0..12
    int bRow = tid >> 4;         // 0..15
    int bCol = (tid & 15) * 4;   // 0..60

    float acc[4][4] = {};
    const float* Ag = g_H1 + (size_t)(m0 + aRow) * HID + k0 + aK;
    const float* Bg = Wi1 + (size_t)(k0 + bRow) * HID + n0 + bCol;

    #pragma unroll 1
    for (int kt = 0; kt < KSLICE1; kt += BK) {
        float4 av = *(const float4*)(Ag + kt);
        float4 bv = *(const float4*)(Bg + (size_t)kt * HID);
        As[aK + 0][aRow] = av.x;
        As[aK + 1][aRow] = av.y;
        As[aK + 2][aRow] = av.z;
        As[aK + 3][aRow] = av.w;
        *(float4*)&Bs[bRow][bCol] = bv;
        __syncthreads();

        #pragma unroll
        for (int k = 0; k < BK; k++) {
            float aF[4], bF[4];
            *(float4*)aF = *(const float4*)&As[k][ty * 4];
            *(float4*)bF = *(const float4*)&Bs[k][tx * 4];
            #pragma unroll
            for (int m = 0; m < 4; m++)
                #pragma unroll
                for (int n = 0; n < 4; n++)
                    acc[m][n] = fmaf(aF[m], bF[n], acc[m][n]);
        }
        __syncthreads();
    }

    float* dst = &g_p1[blockIdx.z][m0 + ty * 4][n0 + tx * 4];
    #pragma unroll
    for (int m = 0; m < 4; m++) {
        float4 o;
        o.x = acc[m][0]; o.y = acc[m][1]; o.z = acc[m][2]; o.w = acc[m][3];
        *(float4*)(dst + (size_t)m * HID) = o;
    }
}

// ---------------------------------------------------------------------------
// K2b: combine gemm1 partials: H2 = relu(sum_slices + bi1).
// One float4 per thread.
// ---------------------------------------------------------------------------
__global__ __launch_bounds__(256)
void combine_kernel(const float* __restrict__ bi1) {
    int gid = blockIdx.x * 256 + threadIdx.x;       // quad index
    int row = gid / (HID / 4);
    if (row >= g_u * BITS) return;
    int col = (gid % (HID / 4)) * 4;

    float4 s = *(const float4*)&g_p1[0][row][col];
    #pragma unroll
    for (int sl = 1; sl < KS1; sl++) {
        float4 t = *(const float4*)&g_p1[sl][row][col];
        s.x += t.x; s.y += t.y; s.z += t.z; s.w += t.w;
    }
    float4 b = *(const float4*)&bi1[col];
    s.x = fmaxf(s.x + b.x, 0.f);
    s.y = fmaxf(s.y + b.y, 0.f);
    s.z = fmaxf(s.z + b.z, 0.f);
    s.w = fmaxf(s.w + b.w, 0.f);
    *(float4*)&g_H2[(size_t)row * HID + col] = s;
}

// ---------------------------------------------------------------------------
// K3a: gemm2 split-K partials. BM=32, BN=64, BK=16, 8 K-slices.
// grid = (128, 8). Thread tile 2x4.
// ---------------------------------------------------------------------------
__global__ __launch_bounds__(256)
void gemm2_kernel(const float* __restrict__ Wi2) {
    const int BM = 32, BK = 16;
    int m0 = blockIdx.x * BM;
    if (m0 >= g_u * BITS) return;
    int slice = blockIdx.y;
    int k0 = slice * KSLICE2;

    __shared__ float As[BK][BM];
    __shared__ float Bs[BK][BITS];

    int tid = threadIdx.x;
    int ty = tid >> 4;           // 0..15 -> rows ty*2..
    int tx = tid & 15;           // 0..15 -> cols tx*4..

    int aRow = tid >> 2;         // 0..63 (only <32 used, tid<128)
    int aK   = (tid & 3) * 4;
    int bRow = tid >> 4;         // 0..15
    int bCol = (tid & 15) * 4;

    float acc[2][4] = {};
    const float* Ag = g_H2 + (size_t)(m0 + (aRow & 31)) * HID + k0 + aK;

    #pragma unroll 1
    for (int kt = 0; kt < KSLICE2; kt += BK) {
        if (tid < 128) {
            float4 av = *(const float4*)(Ag + kt);
            As[aK + 0][aRow] = av.x;
            As[aK + 1][aRow] = av.y;
            As[aK + 2][aRow] = av.z;
            As[aK + 3][aRow] = av.w;
        }
        float4 bv = *(const float4*)(Wi2 + (size_t)(k0 + kt + bRow) * BITS + bCol);
        *(float4*)&Bs[bRow][bCol] = bv;
        __syncthreads();

        #pragma unroll
        for (int k = 0; k < BK; k++) {
            float aF[2], bF[4];
            aF[0] = As[k][ty * 2 + 0];
            aF[1] = As[k][ty * 2 + 1];
            *(float4*)bF = *(const float4*)&Bs[k][tx * 4];
            #pragma unroll
            for (int m = 0; m < 2; m++)
                #pragma unroll
                for (int n = 0; n < 4; n++)
                    acc[m][n] = fmaf(aF[m], bF[n], acc[m][n]);
        }
        __syncthreads();
    }

    #pragma unroll
    for (int m = 0; m < 2; m++) {
        float4 o;
        o.x = acc[m][0]; o.y = acc[m][1]; o.z = acc[m][2]; o.w = acc[m][3];
        *(float4*)&g_part[slice][m0 + ty * 2 + m][tx * 4] = o;
    }
}

// ---------------------------------------------------------------------------
// K3b: sum slices + bias, per-row argmax (first-max semantics).
// One warp per row.
// ---------------------------------------------------------------------------
__global__ __launch_bounds__(256)
void argmax_kernel(const float* __restrict__ bi2) {
    int warp = threadIdx.x >> 5;
    int lane = threadIdx.x & 31;
    int row = blockIdx.x * 8 + warp;
    if (row >= g_u * BITS) return;

    float v0 = bi2[lane];
    float v1 = bi2[lane + 32];
    #pragma unroll
    for (int s = 0; s < KS2; s++) {
        v0 += g_part[s][row][lane];
        v1 += g_part[s][row][lane + 32];
    }
    float best = v0; int bi = lane;
    if (v1 > best) { best = v1; bi = lane + 32; }

    #pragma unroll
    for (int off = 16; off > 0; off >>= 1) {
        float ob = __shfl_down_sync(0xffffffff, best, off);
        int   oi = __shfl_down_sync(0xffffffff, bi, off);
        if (ob > best || (ob == best && oi < bi)) { best = ob; bi = oi; }
    }
    if (lane == 0) g_idx[row] = bi;
}

// ---------------------------------------------------------------------------
// K4: out[b,i] = a_bits[b, idx[slot,i]] * valid[slot,i]. float4 stores.
// ---------------------------------------------------------------------------
__global__ __launch_bounds__(256)
void out_kernel(const float* __restrict__ a_bits, const int* __restrict__ shift,
                float* __restrict__ out, int nquads) {
    int gid = blockIdx.x * 256 + threadIdx.x;
    if (gid >= nquads) return;
    int b = gid >> 4;
    int i0 = (gid & 15) * 4;
    int sl = g_pred_slot[shift[b]];
    int tb = (sl << 6) + i0;
    const float* arow = a_bits + ((size_t)b << 6);
    float4 o;
    o.x = arow[g_idx[tb + 0]] * g_valid[tb + 0];
    o.y = arow[g_idx[tb + 1]] * g_valid[tb + 1];
    o.z = arow[g_idx[tb + 2]] * g_valid[tb + 2];
    o.w = arow[g_idx[tb + 3]] * g_valid[tb + 3];
    ((float4*)out)[gid] = o;
}

// ---------------------------------------------------------------------------
extern "C" void kernel_launch(void* const* d_in, const int* in_sizes, int n_in,
                              void* d_out, int out_size) {
    const float* a_bits = (const float*)d_in[0];
    const int*   shift  = (const int*)d_in[1];
    const float* Ws0 = (const float*)d_in[2];
    const float* bs0 = (const float*)d_in[3];
    const float* Ws1 = (const float*)d_in[4];
    const float* bs1 = (const float*)d_in[5];
    const float* Ws2 = (const float*)d_in[6];
    const float* bs2 = (const float*)d_in[7];
    const float* Wi0 = (const float*)d_in[8];
    const float* bi0 = (const float*)d_in[9];
    const float* Wi1 = (const float*)d_in[10];
    const float* bi1 = (const float*)d_in[11];
    const float* Wi2 = (const float*)d_in[12];
    const float* bi2 = (const float*)d_in[13];
    const float* Wv0 = (const float*)d_in[14];
    const float* bv0 = (const float*)d_in[15];
    const float* Wv1 = (const float*)d_in[16];
    const float* bv1 = (const float*)d_in[17];
    float* out = (float*)d_out;

    int B = in_sizes[1];               // 32768
    int nquads = B * (BITS / 4);

    decoder_kernel<<<BITS, 256>>>(Ws0, bs0, Ws1, bs1, Ws2, bs2);
    compact_kernel<<<1, BITS>>>();
    table_kernel<<<T_ROWS, 256>>>(Wi0, bi0, Wv0, bv0, Wv1, bv1);

    dim3 g1(HID / 64, T_ROWS / 64, KS1);        // (12, 64, 4)
    gemm1_kernel<<<g1, 256>>>(Wi1);
    combine_kernel<<<T_ROWS * (HID / 4) / 256, 256>>>(bi1);

    dim3 g2(T_ROWS / 32, KS2);                  // (128, 8)
    gemm2_kernel<<<g2, 256>>>(Wi2);
    argmax_kernel<<<T_ROWS / 8, 256>>>(bi2);

    out_kernel<<<(nquads + 255) / 256, 256>>>(a_bits, shift, out, nquads);
}

// round 4
// speedup vs baseline: 3.4880x; 1.4922x over previous
#include <cuda_runtime.h>
#include <cuda_bf16.h>
#include <math.h>

// ---------------------------------------------------------------------------
// FrozenLSLModel == (pred, out_pos) lookup table (u <= 64 distinct preds).
// R4: decoder as split-K GEMM; H1 and combine fused into GEMM A-loads;
// warp-shuffle output gather.
// ---------------------------------------------------------------------------

#define HID 768
#define BITS 64
#define T_ROWS (BITS * BITS)

#define KSD 4                    // decoder l1 K-slices
#define KSLICED (HID / KSD)      // 192
#define KS1 6                    // gemm1 K-slices
#define KSLICE1 (HID / KS1)      // 128
#define KS2 8                    // gemm2 K-slices
#define KSLICE2 (HID / KS2)      // 96

__device__ float g_d1[KSD][BITS][HID];        // decoder l1 partials
__device__ float g_p1[KS1][T_ROWS][HID];      // gemm1 partials
__device__ float g_part[KS2][T_ROWS][BITS];   // gemm2 partials
__device__ float g_valid[T_ROWS];
__device__ int   g_idx[T_ROWS];
__device__ int   g_pred[BITS];
__device__ int   g_u;
__device__ int   g_plist[BITS];
__device__ int   g_pred_slot[BITS];

// ---------------------------------------------------------------------------
// D1: decoder layer1 as split-K GEMM. A[s,k] = relu(bs0[k] + sum_bits Ws0),
// computed on the fly. BM=64(all s) x BN=64, BK=16, grid (12, KSD).
// ---------------------------------------------------------------------------
__global__ __launch_bounds__(256)
void dec_l1_kernel(const float* __restrict__ Ws0, const float* __restrict__ bs0,
                   const float* __restrict__ Ws1) {
    const int BK = 16;
    int n0 = blockIdx.x * 64;
    int k0 = blockIdx.y * KSLICED;

    __shared__ float As[BK][64];
    __shared__ float Bs[BK][64];

    int tid = threadIdx.x;
    int ty = tid >> 4, tx = tid & 15;
    int aRow = tid >> 2;          // s value 0..63
    int aK   = (tid & 3) * 4;
    int bRow = tid >> 4;
    int bCol = (tid & 15) * 4;

    float acc[4][4] = {};

    #pragma unroll 1
    for (int kt = 0; kt < KSLICED; kt += BK) {
        int gk = k0 + kt + aK;
        float4 v = *(const float4*)(bs0 + gk);
        #pragma unroll
        for (int b = 0; b < 6; b++) {
            if ((aRow >> b) & 1) {
                float4 w = *(const float4*)(Ws0 + (size_t)b * HID + gk);
                v.x += w.x; v.y += w.y; v.z += w.z; v.w += w.w;
            }
        }
        As[aK + 0][aRow] = fmaxf(v.x, 0.f);
        As[aK + 1][aRow] = fmaxf(v.y, 0.f);
        As[aK + 2][aRow] = fmaxf(v.z, 0.f);
        As[aK + 3][aRow] = fmaxf(v.w, 0.f);
        float4 bv = *(const float4*)(Ws1 + (size_t)(k0 + kt + bRow) * HID + n0 + bCol);
        *(float4*)&Bs[bRow][bCol] = bv;
        __syncthreads();

        #pragma unroll
        for (int k = 0; k < BK; k++) {
            float aF[4], bF[4];
            *(float4*)aF = *(const float4*)&As[k][ty * 4];
            *(float4*)bF = *(const float4*)&Bs[k][tx * 4];
            #pragma unroll
            for (int m = 0; m < 4; m++)
                #pragma unroll
                for (int n = 0; n < 4; n++)
                    acc[m][n] = fmaf(aF[m], bF[n], acc[m][n]);
        }
        __syncthreads();
    }

    #pragma unroll
    for (int m = 0; m < 4; m++) {
        float4 o;
        o.x = acc[m][0]; o.y = acc[m][1]; o.z = acc[m][2]; o.w = acc[m][3];
        *(float4*)&g_d1[blockIdx.y][ty * 4 + m][n0 + tx * 4] = o;
    }
}

// ---------------------------------------------------------------------------
// D2: decoder layer2 + argmax. One block per s.
// ---------------------------------------------------------------------------
__global__ __launch_bounds__(256)
void dec_l2_kernel(const float* __restrict__ bs1,
                   const float* __restrict__ Ws2, const float* __restrict__ bs2) {
    int s = blockIdx.x;
    int tid = threadIdx.x;
    __shared__ float h1[HID];
    __shared__ float part[4][BITS];
    __shared__ float lg[BITS];

    #pragma unroll
    for (int r = 0; r < 3; r++) {
        int j = tid + r * 256;
        float v = bs1[j];
        #pragma unroll
        for (int sl = 0; sl < KSD; sl++) v += g_d1[sl][s][j];
        h1[j] = fmaxf(v, 0.f);
    }
    __syncthreads();

    int col = tid & 63;
    int chunk = tid >> 6;                 // 0..3
    float p = 0.f;
    int kb = chunk * (HID / 4);
    for (int k = 0; k < HID / 4; k++)
        p = fmaf(h1[kb + k], Ws2[(size_t)(kb + k) * BITS + col], p);
    part[chunk][col] = p;
    __syncthreads();

    if (tid < BITS)
        lg[tid] = part[0][tid] + part[1][tid] + part[2][tid] + part[3][tid] + bs2[tid];
    __syncthreads();

    if (tid == 0) {
        float best = lg[0]; int bi = 0;
        for (int c = 1; c < BITS; c++)
            if (lg[c] > best) { best = lg[c]; bi = c; }
        g_pred[s] = bi;
    }
}

// ---------------------------------------------------------------------------
// compact distinct preds -> slots.
// ---------------------------------------------------------------------------
__global__ void compact_kernel() {
    __shared__ int used[BITS];
    __shared__ int slot[BITS];
    int tid = threadIdx.x;
    used[tid] = 0;
    __syncthreads();
    int pr = g_pred[tid];
    used[pr] = 1;
    __syncthreads();
    if (tid == 0) {
        int u = 0;
        for (int p = 0; p < BITS; p++)
            if (used[p]) { g_plist[u] = p; slot[p] = u; u++; }
        g_u = u;
    }
    __syncthreads();
    g_pred_slot[tid] = slot[pr];
}

// ---------------------------------------------------------------------------
// validity table only (H1 now fused into gemm1).
// ---------------------------------------------------------------------------
__global__ __launch_bounds__(128)
void valid_kernel(const float* __restrict__ Wv0, const float* __restrict__ bv0,
                  const float* __restrict__ Wv1, const float* __restrict__ bv1) {
    int t = blockIdx.x;
    int sl = t >> 6;
    if (sl >= g_u) return;
    int p = g_plist[sl];
    int i = t & 63;
    int tid = threadIdx.x;

    const float* vp = Wv0 + (size_t)(BITS + p) * (HID / 2);
    const float* vi = Wv0 + (size_t)i * (HID / 2);
    float part = 0.f;
    for (int j = tid; j < HID / 2; j += 128)
        part += fmaxf(vp[j] + vi[j] + bv0[j], 0.f) * Wv1[j];

    __shared__ float red[128];
    red[tid] = part;
    __syncthreads();
    for (int off = 64; off > 0; off >>= 1) {
        if (tid < off) red[tid] += red[tid + off];
        __syncthreads();
    }
    if (tid == 0) {
        float v = red[0] + bv1[0];
        g_valid[t] = 1.f / (1.f + expf(-v));
    }
}

// ---------------------------------------------------------------------------
// G1: gemm1 split-K, H1 fused into A-load (p constant per block).
// BM=64, BN=64, BK=16, grid (12, 64, KS1), register-prefetch double buffer.
// ---------------------------------------------------------------------------
__global__ __launch_bounds__(256)
void gemm1_kernel(const float* __restrict__ Wi0, const float* __restrict__ bi0,
                  const float* __restrict__ Wi1) {
    const int BK = 16;
    int sl = blockIdx.y;
    if (sl >= g_u) return;
    int p = g_plist[sl];
    int m0 = sl * 64;
    int n0 = blockIdx.x * 64;
    int k0 = blockIdx.z * KSLICE1;

    __shared__ float As[2][BK][64];
    __shared__ float Bs[2][BK][64];

    int tid = threadIdx.x;
    int ty = tid >> 4, tx = tid & 15;
    int aRow = tid >> 2;            // i = 0..63
    int aK   = (tid & 3) * 4;
    int bRow = tid >> 4;
    int bCol = (tid & 15) * 4;

    const float* Wp = Wi0 + (size_t)(BITS + p) * HID;
    const float* Wi = Wi0 + (size_t)aRow * HID;

    float acc[4][4] = {};

    // prime buffer 0
    {
        int gk = k0 + aK;
        float4 wp = *(const float4*)(Wp + gk);
        float4 wi = *(const float4*)(Wi + gk);
        float4 b0 = *(const float4*)(bi0 + gk);
        As[0][aK + 0][aRow] = fmaxf(wp.x + wi.x + b0.x, 0.f);
        As[0][aK + 1][aRow] = fmaxf(wp.y + wi.y + b0.y, 0.f);
        As[0][aK + 2][aRow] = fmaxf(wp.z + wi.z + b0.z, 0.f);
        As[0][aK + 3][aRow] = fmaxf(wp.w + wi.w + b0.w, 0.f);
        float4 bv = *(const float4*)(Wi1 + (size_t)(k0 + bRow) * HID + n0 + bCol);
        *(float4*)&Bs[0][bRow][bCol] = bv;
    }
    __syncthreads();

    int cur = 0;
    #pragma unroll 1
    for (int kt = 0; kt < KSLICE1; kt += BK) {
        float4 wp, wi, b0, bv;
        bool more = (kt + BK) < KSLICE1;
        if (more) {
            int gk = k0 + kt + BK + aK;
            wp = *(const float4*)(Wp + gk);
            wi = *(const float4*)(Wi + gk);
            b0 = *(const float4*)(bi0 + gk);
            bv = *(const float4*)(Wi1 + (size_t)(k0 + kt + BK + bRow) * HID + n0 + bCol);
        }

        #pragma unroll
        for (int k = 0; k < BK; k++) {
            float aF[4], bF[4];
            *(float4*)aF = *(const float4*)&As[cur][k][ty * 4];
            *(float4*)bF = *(const float4*)&Bs[cur][k][tx * 4];
            #pragma unroll
            for (int m = 0; m < 4; m++)
                #pragma unroll
                for (int n = 0; n < 4; n++)
                    acc[m][n] = fmaf(aF[m], bF[n], acc[m][n]);
        }

        if (more) {
            int nxt = cur ^ 1;
            As[nxt][aK + 0][aRow] = fmaxf(wp.x + wi.x + b0.x, 0.f);
            As[nxt][aK + 1][aRow] = fmaxf(wp.y + wi.y + b0.y, 0.f);
            As[nxt][aK + 2][aRow] = fmaxf(wp.z + wi.z + b0.z, 0.f);
            As[nxt][aK + 3][aRow] = fmaxf(wp.w + wi.w + b0.w, 0.f);
            *(float4*)&Bs[nxt][bRow][bCol] = bv;
        }
        __syncthreads();
        cur ^= 1;
    }

    float* dst = &g_p1[blockIdx.z][m0 + ty * 4][n0 + tx * 4];
    #pragma unroll
    for (int m = 0; m < 4; m++) {
        float4 o;
        o.x = acc[m][0]; o.y = acc[m][1]; o.z = acc[m][2]; o.w = acc[m][3];
        *(float4*)(dst + (size_t)m * HID) = o;
    }
}

// ---------------------------------------------------------------------------
// G2: gemm2 split-K; combine (sum KS1 partials + bias + relu) fused into
// A-load. BM=32, BN=64, BK=16, grid (128, KS2).
// ---------------------------------------------------------------------------
__global__ __launch_bounds__(256)
void gemm2_kernel(const float* __restrict__ bi1, const float* __restrict__ Wi2) {
    const int BM = 32, BK = 16;
    int m0 = blockIdx.x * BM;
    if (m0 >= g_u * BITS) return;
    int k0 = blockIdx.y * KSLICE2;

    __shared__ float As[BK][BM];
    __shared__ float Bs[BK][BITS];

    int tid = threadIdx.x;
    int ty = tid >> 4, tx = tid & 15;
    int aRow = (tid >> 2) & 31;
    int aK   = (tid & 3) * 4;
    int bRow = tid >> 4;
    int bCol = (tid & 15) * 4;

    float acc[2][4] = {};

    #pragma unroll 1
    for (int kt = 0; kt < KSLICE2; kt += BK) {
        if (tid < 128) {
            int gk = k0 + kt + aK;
            int m = m0 + aRow;
            float4 s = *(const float4*)&g_p1[0][m][gk];
            #pragma unroll
            for (int sl = 1; sl < KS1; sl++) {
                float4 t = *(const float4*)&g_p1[sl][m][gk];
                s.x += t.x; s.y += t.y; s.z += t.z; s.w += t.w;
            }
            float4 b = *(const float4*)(bi1 + gk);
            As[aK + 0][aRow] = fmaxf(s.x + b.x, 0.f);
            As[aK + 1][aRow] = fmaxf(s.y + b.y, 0.f);
            As[aK + 2][aRow] = fmaxf(s.z + b.z, 0.f);
            As[aK + 3][aRow] = fmaxf(s.w + b.w, 0.f);
        }
        float4 bv = *(const float4*)(Wi2 + (size_t)(k0 + kt + bRow) * BITS + bCol);
        *(float4*)&Bs[bRow][bCol] = bv;
        __syncthreads();

        #pragma unroll
        for (int k = 0; k < BK; k++) {
            float aF[2], bF[4];
            aF[0] = As[k][ty * 2 + 0];
            aF[1] = As[k][ty * 2 + 1];
            *(float4*)bF = *(const float4*)&Bs[k][tx * 4];
            #pragma unroll
            for (int m = 0; m < 2; m++)
                #pragma unroll
                for (int n = 0; n < 4; n++)
                    acc[m][n] = fmaf(aF[m], bF[n], acc[m][n]);
        }
        __syncthreads();
    }

    #pragma unroll
    for (int m = 0; m < 2; m++) {
        float4 o;
        o.x = acc[m][0]; o.y = acc[m][1]; o.z = acc[m][2]; o.w = acc[m][3];
        *(float4*)&g_part[blockIdx.y][m0 + ty * 2 + m][tx * 4] = o;
    }
}

// ---------------------------------------------------------------------------
// argmax over summed gemm2 partials. One warp per table row.
// ---------------------------------------------------------------------------
__global__ __launch_bounds__(256)
void argmax_kernel(const float* __restrict__ bi2) {
    int warp = threadIdx.x >> 5;
    int lane = threadIdx.x & 31;
    int row = blockIdx.x * 8 + warp;
    if (row >= g_u * BITS) return;

    float v0 = bi2[lane];
    float v1 = bi2[lane + 32];
    #pragma unroll
    for (int s = 0; s < KS2; s++) {
        v0 += g_part[s][row][lane];
        v1 += g_part[s][row][lane + 32];
    }
    float best = v0; int bi = lane;
    if (v1 > best) { best = v1; bi = lane + 32; }

    #pragma unroll
    for (int off = 16; off > 0; off >>= 1) {
        float ob = __shfl_down_sync(0xffffffff, best, off);
        int   oi = __shfl_down_sync(0xffffffff, bi, off);
        if (ob > best || (ob == best && oi < bi)) { best = ob; bi = oi; }
    }
    if (lane == 0) g_idx[row] = bi;
}

// ---------------------------------------------------------------------------
// out: warp per batch row; row in 2 regs/lane; gather via shfl.
// ---------------------------------------------------------------------------
__global__ __launch_bounds__(256)
void out_kernel(const float* __restrict__ a_bits, const int* __restrict__ shift,
                float* __restrict__ out, int B) {
    int warp = threadIdx.x >> 5;
    int lane = threadIdx.x & 31;
    int b = blockIdx.x * 8 + warp;
    if (b >= B) return;

    const float* arow = a_bits + ((size_t)b << 6);
    float a0 = arow[lane];
    float a1 = arow[lane + 32];
    int sl = g_pred_slot[shift[b]];
    int tb = sl << 6;

    int   i0 = g_idx[tb + lane];
    int   i1 = g_idx[tb + lane + 32];
    float v0 = g_valid[tb + lane];
    float v1 = g_valid[tb + lane + 32];

    float c00 = __shfl_sync(0xffffffff, a0, i0 & 31);
    float c01 = __shfl_sync(0xffffffff, a1, i0 & 31);
    float c10 = __shfl_sync(0xffffffff, a0, i1 & 31);
    float c11 = __shfl_sync(0xffffffff, a1, i1 & 31);

    float g0 = (i0 < 32) ? c00 : c01;
    float g1 = (i1 < 32) ? c10 : c11;

    out[((size_t)b << 6) + lane]      = g0 * v0;
    out[((size_t)b << 6) + lane + 32] = g1 * v1;
}

// ---------------------------------------------------------------------------
extern "C" void kernel_launch(void* const* d_in, const int* in_sizes, int n_in,
                              void* d_out, int out_size) {
    const float* a_bits = (const float*)d_in[0];
    const int*   shift  = (const int*)d_in[1];
    const float* Ws0 = (const float*)d_in[2];
    const float* bs0 = (const float*)d_in[3];
    const float* Ws1 = (const float*)d_in[4];
    const float* bs1 = (const float*)d_in[5];
    const float* Ws2 = (const float*)d_in[6];
    const float* bs2 = (const float*)d_in[7];
    const float* Wi0 = (const float*)d_in[8];
    const float* bi0 = (const float*)d_in[9];
    const float* Wi1 = (const float*)d_in[10];
    const float* bi1 = (const float*)d_in[11];
    const float* Wi2 = (const float*)d_in[12];
    const float* bi2 = (const float*)d_in[13];
    const float* Wv0 = (const float*)d_in[14];
    const float* bv0 = (const float*)d_in[15];
    const float* Wv1 = (const float*)d_in[16];
    const float* bv1 = (const float*)d_in[17];
    float* out = (float*)d_out;

    int B = in_sizes[1];               // 32768

    dim3 gd(HID / 64, KSD);                        // (12, 4)
    dec_l1_kernel<<<gd, 256>>>(Ws0, bs0, Ws1);
    dec_l2_kernel<<<BITS, 256>>>(bs1, Ws2, bs2);
    compact_kernel<<<1, BITS>>>();
    valid_kernel<<<T_ROWS, 128>>>(Wv0, bv0, Wv1, bv1);

    dim3 g1(HID / 64, BITS, KS1);                  // (12, 64, 6)
    gemm1_kernel<<<g1, 256>>>(Wi0, bi0, Wi1);

    dim3 g2(T_ROWS / 32, KS2);                     // (128, 8)
    gemm2_kernel<<<g2, 256>>>(bi1, Wi2);
    argmax_kernel<<<T_ROWS / 8, 256>>>(bi2);

    out_kernel<<<(B + 7) / 8, 256>>>(a_bits, shift, out, B);
}